// round 4
// baseline (speedup 1.0000x reference)
#include <cuda_runtime.h>
#include <cstdint>

// AFM forward:
//   idx = x + offsets; emb = E[idx]  (B,24,16)
//   linear = sum_f L[idx] + lb
//   inner_p = emb_r * emb_c (elementwise), p over 276 pairs
//   h = relu(inner @ W + b)   (276,32)
//   s_p = h @ pw + pb
//   attn = softmax_p(s)
//   out = linear + sum_p attn_p * (inner_p . fc_w) + fc_b
//
// cross term = (sum_p e^{s_p} * g_p) / (sum_p e^{s_p}), g_p = inner_p . fc_w
// (pooled vector never materialized)

#define NF 24
#define NE 16
#define NA 32
#define NP 276            // 24*23/2
#define NTHREADS 288      // 9 warps, one thread per pair

__global__ __launch_bounds__(NTHREADS) void afm_kernel(
    const int* __restrict__ x_raw,            // [B,24] int32 OR int64 (auto-detect)
    const float* __restrict__ embed_table,    // [V,16]
    const float* __restrict__ linear_table,   // [V,1]
    const float* __restrict__ linear_bias,    // [1]
    const float* __restrict__ attn_W,         // [16,32]
    const float* __restrict__ attn_b,         // [32]
    const float* __restrict__ proj_w,         // [32,1]
    const float* __restrict__ proj_b,         // [1]
    const float* __restrict__ fc_w,           // [16,1]
    const float* __restrict__ fc_b,           // [1]
    float* __restrict__ out)                  // [B,1]
{
    __shared__ float s_emb[NF][NE];          // 1536 B
    __shared__ float s_W[NE][NA];            // 2048 B
    __shared__ int   s_gid[NF];
    __shared__ float s_lin[NF];
    __shared__ float s_attnb[NA];
    __shared__ float s_projw[NA];
    __shared__ float s_fcw[NE];
    __shared__ float s_scal[2];
    __shared__ float red_max[9];
    __shared__ float red_se[9];
    __shared__ float red_sg[9];
    __shared__ float s_bcast[1];

    const int b    = blockIdx.x;
    const int tid  = threadIdx.x;
    const int wid  = tid >> 5;
    const int lane = tid & 31;

    // dtype probe: int64 values < 50000 have zero high words at odd positions.
    const bool is64 = (x_raw[1] == 0) & (x_raw[3] == 0) & (x_raw[5] == 0) & (x_raw[7] == 0);

    // ---- stage indices, linear terms, weights ----
    if (tid < NF) {
        int xv;
        if (is64) xv = x_raw[((long long)b * NF + tid) * 2];   // low word of int64
        else      xv = x_raw[(long long)b * NF + tid];
        int gid = xv + tid * 50000;
        s_gid[tid] = gid;
        s_lin[tid] = linear_table[gid];
    }
    for (int t = tid; t < NE * NA; t += NTHREADS)
        ((float*)s_W)[t] = attn_W[t];
    if (tid < NA) {
        s_attnb[tid] = attn_b[tid];
        s_projw[tid] = proj_w[tid];
    }
    if (tid < NE) s_fcw[tid] = fc_w[tid];
    if (tid == 0) {
        s_scal[0] = proj_b[0];
        s_scal[1] = fc_b[0] + linear_bias[0];
    }
    __syncthreads();

    // ---- gather embeddings as float4 (24 rows x 4 float4) ----
    for (int t = tid; t < NF * 4; t += NTHREADS) {
        int f = t >> 2, q = t & 3;
        const float4* src = (const float4*)embed_table;
        ((float4*)&s_emb[f][0])[q] = src[(long long)s_gid[f] * 4 + q];
    }
    __syncthreads();

    // ---- per-pair compute ----
    const bool active = (tid < NP);
    float sc = -1e30f;   // score (for softmax max)
    float g  = 0.f;      // inner . fc_w

    if (active) {
        // decode pair (r,c) from linear index
        int p = tid, r = 0, base = 0;
        while (p >= base + (NF - 1 - r)) { base += NF - 1 - r; r++; }
        int c = r + 1 + (p - base);

        float inner[NE];
        {
            const float4* er = (const float4*)&s_emb[r][0];
            const float4* ec = (const float4*)&s_emb[c][0];
            #pragma unroll
            for (int q = 0; q < 4; q++) {
                float4 a = er[q], bb = ec[q];
                inner[q*4+0] = a.x * bb.x;
                inner[q*4+1] = a.y * bb.y;
                inner[q*4+2] = a.z * bb.z;
                inner[q*4+3] = a.w * bb.w;
            }
        }

        // g = inner . fc_w
        #pragma unroll
        for (int e = 0; e < NE; e++) g += inner[e] * s_fcw[e];

        // h = inner @ W + b ; relu ; s = h . proj_w + proj_b
        float h[NA];
        #pragma unroll
        for (int a = 0; a < NA; a++) h[a] = s_attnb[a];
        #pragma unroll
        for (int e = 0; e < NE; e++) {
            float ie = inner[e];
            const float4* wrow = (const float4*)&s_W[e][0];
            #pragma unroll
            for (int q = 0; q < 8; q++) {
                float4 w = wrow[q];
                h[q*4+0] = fmaf(ie, w.x, h[q*4+0]);
                h[q*4+1] = fmaf(ie, w.y, h[q*4+1]);
                h[q*4+2] = fmaf(ie, w.z, h[q*4+2]);
                h[q*4+3] = fmaf(ie, w.w, h[q*4+3]);
            }
        }
        float s = s_scal[0];
        #pragma unroll
        for (int a = 0; a < NA; a++)
            s = fmaf(fmaxf(h[a], 0.f), s_projw[a], s);
        sc = s;
    }

    // ---- block softmax-max reduction ----
    float m = sc;
    #pragma unroll
    for (int o = 16; o > 0; o >>= 1)
        m = fmaxf(m, __shfl_xor_sync(0xffffffffu, m, o));
    if (lane == 0) red_max[wid] = m;
    __syncthreads();
    if (tid == 0) {
        float mm = red_max[0];
        #pragma unroll
        for (int w = 1; w < 9; w++) mm = fmaxf(mm, red_max[w]);
        s_bcast[0] = mm;
    }
    __syncthreads();
    const float smax = s_bcast[0];

    // ---- exp + weighted sums ----
    float ex = active ? __expf(sc - smax) : 0.f;
    float eg = ex * g;
    float se = ex, sg = eg;
    #pragma unroll
    for (int o = 16; o > 0; o >>= 1) {
        se += __shfl_xor_sync(0xffffffffu, se, o);
        sg += __shfl_xor_sync(0xffffffffu, sg, o);
    }
    if (lane == 0) { red_se[wid] = se; red_sg[wid] = sg; }
    __syncthreads();

    if (tid == 0) {
        float tse = 0.f, tsg = 0.f;
        #pragma unroll
        for (int w = 0; w < 9; w++) { tse += red_se[w]; tsg += red_sg[w]; }
        float lin = 0.f;
        #pragma unroll
        for (int f = 0; f < NF; f++) lin += s_lin[f];
        out[b] = lin + s_scal[1] + tsg / tse;
    }
}

extern "C" void kernel_launch(void* const* d_in, const int* in_sizes, int n_in,
                              void* d_out, int out_size) {
    const int* x              = (const int*)d_in[0];
    const float* embed_table  = (const float*)d_in[1];
    const float* linear_table = (const float*)d_in[2];
    const float* linear_bias  = (const float*)d_in[3];
    const float* attn_W       = (const float*)d_in[4];
    const float* attn_b       = (const float*)d_in[5];
    const float* proj_w       = (const float*)d_in[6];
    const float* proj_b       = (const float*)d_in[7];
    const float* fc_w         = (const float*)d_in[8];
    const float* fc_b         = (const float*)d_in[9];
    float* out = (float*)d_out;

    int B = in_sizes[0] / NF;
    afm_kernel<<<B, NTHREADS>>>(x, embed_table, linear_table, linear_bias,
                                attn_W, attn_b, proj_w, proj_b, fc_w, fc_b, out);
}

// round 5
// speedup vs baseline: 1.3215x; 1.3215x over previous
#include <cuda_runtime.h>
#include <cstdint>

// AFM forward, 2 samples per CTA, one thread per (pair, 2 samples).
// cross term = (sum_p e^{s_p} g_p) / (sum_p e^{s_p}),  g_p = inner_p . fc_w

#define NF 24
#define NE 16
#define NA 32
#define NP 276            // 24*23/2
#define NS 2              // samples per block
#define NTHREADS 288      // 9 warps, one thread per pair
#define NWARP 9

__global__ __launch_bounds__(NTHREADS) void afm_kernel(
    const int* __restrict__ x_raw,            // [B,24] int32 OR int64 (auto-detect)
    const float* __restrict__ embed_table,    // [V,16]
    const float* __restrict__ linear_table,   // [V,1]
    const float* __restrict__ linear_bias,    // [1]
    const float* __restrict__ attn_W,         // [16,32]
    const float* __restrict__ attn_b,         // [32]
    const float* __restrict__ proj_w,         // [32,1]
    const float* __restrict__ proj_b,         // [1]
    const float* __restrict__ fc_w,           // [16,1]
    const float* __restrict__ fc_b,           // [1]
    float* __restrict__ out)                  // [B,1]
{
    __shared__ float s_emb[NS][NF][NE];       // 3 KB
    __shared__ float s_W[NE][NA];             // 2 KB
    __shared__ int   s_gid[NS][NF];
    __shared__ float s_lin[NS][NF];
    __shared__ float s_attnb[NA];
    __shared__ float s_projw[NA];
    __shared__ float s_fcw[NE];
    __shared__ float s_scal[2];
    __shared__ float red_max[NS][NWARP];
    __shared__ float red_se[NS][NWARP];
    __shared__ float red_sg[NS][NWARP];
    __shared__ float s_smax[NS];

    const int tid  = threadIdx.x;
    const int wid  = tid >> 5;
    const int lane = tid & 31;
    const long long b0 = (long long)blockIdx.x * NS;

    // dtype probe: int64 values < 50000 have zero high words at odd positions.
    const bool is64 = (x_raw[1] == 0) & (x_raw[3] == 0) & (x_raw[5] == 0) & (x_raw[7] == 0);

    // ---- stage indices + linear terms (48 threads) ----
    if (tid < NS * NF) {
        int s = tid >> 4 >= 0 ? tid / NF : 0;   // s = tid / 24
        s = tid / NF;
        int f = tid - s * NF;
        long long flat = (b0 + s) * NF + f;
        int xv = is64 ? x_raw[flat * 2] : x_raw[flat];
        int gid = xv + f * 50000;
        s_gid[s][f] = gid;
        s_lin[s][f] = linear_table[gid];
    }
    for (int t = tid; t < NE * NA; t += NTHREADS)
        ((float*)s_W)[t] = attn_W[t];
    if (tid < NA) {
        s_attnb[tid] = attn_b[tid];
        s_projw[tid] = proj_w[tid];
    }
    if (tid < NE) s_fcw[tid] = fc_w[tid];
    if (tid == 0) {
        s_scal[0] = proj_b[0];
        s_scal[1] = fc_b[0] + linear_bias[0];
    }
    __syncthreads();

    // ---- gather embeddings as float4: NS*24 rows x 4 float4 = 192 loads ----
    if (tid < NS * NF * 4) {
        int t = tid;
        int s = t / (NF * 4);
        int rem = t - s * (NF * 4);
        int f = rem >> 2, q = rem & 3;
        const float4* src = (const float4*)embed_table;
        ((float4*)&s_emb[s][f][0])[q] = src[(long long)s_gid[s][f] * 4 + q];
    }
    __syncthreads();

    // ---- per-pair compute (pair tid, both samples) ----
    const bool active = (tid < NP);
    float sc0 = -1e30f, sc1 = -1e30f;
    float g0 = 0.f, g1 = 0.f;

    if (active) {
        int p = tid, r = 0, base = 0;
        while (p >= base + (NF - 1 - r)) { base += NF - 1 - r; r++; }
        int c = r + 1 + (p - base);

        float in0[NE], in1[NE];
        {
            const float4* er0 = (const float4*)&s_emb[0][r][0];
            const float4* ec0 = (const float4*)&s_emb[0][c][0];
            const float4* er1 = (const float4*)&s_emb[1][r][0];
            const float4* ec1 = (const float4*)&s_emb[1][c][0];
            #pragma unroll
            for (int q = 0; q < 4; q++) {
                float4 a0 = er0[q], b0v = ec0[q];
                float4 a1 = er1[q], b1v = ec1[q];
                in0[q*4+0] = a0.x * b0v.x;  in1[q*4+0] = a1.x * b1v.x;
                in0[q*4+1] = a0.y * b0v.y;  in1[q*4+1] = a1.y * b1v.y;
                in0[q*4+2] = a0.z * b0v.z;  in1[q*4+2] = a1.z * b1v.z;
                in0[q*4+3] = a0.w * b0v.w;  in1[q*4+3] = a1.w * b1v.w;
            }
        }

        // g = inner . fc_w
        #pragma unroll
        for (int e = 0; e < NE; e++) {
            float fw = s_fcw[e];
            g0 = fmaf(in0[e], fw, g0);
            g1 = fmaf(in1[e], fw, g1);
        }

        // h = relu(inner @ W + b); s = h . proj_w + proj_b
        // chunked over 4 chunks of 8 attn columns, W loads shared by both samples
        float s0 = s_scal[0], s1 = s_scal[0];
        #pragma unroll
        for (int ch = 0; ch < 4; ch++) {
            float4 bA = ((const float4*)s_attnb)[ch*2+0];
            float4 bB = ((const float4*)s_attnb)[ch*2+1];
            float h0[8], h1[8];
            h0[0]=bA.x; h0[1]=bA.y; h0[2]=bA.z; h0[3]=bA.w;
            h0[4]=bB.x; h0[5]=bB.y; h0[6]=bB.z; h0[7]=bB.w;
            #pragma unroll
            for (int j = 0; j < 8; j++) h1[j] = h0[j];

            #pragma unroll
            for (int e = 0; e < NE; e++) {
                const float4* wrow = (const float4*)&s_W[e][0];
                float4 wA = wrow[ch*2+0];
                float4 wB = wrow[ch*2+1];
                float i0 = in0[e], i1 = in1[e];
                h0[0] = fmaf(i0, wA.x, h0[0]);  h1[0] = fmaf(i1, wA.x, h1[0]);
                h0[1] = fmaf(i0, wA.y, h0[1]);  h1[1] = fmaf(i1, wA.y, h1[1]);
                h0[2] = fmaf(i0, wA.z, h0[2]);  h1[2] = fmaf(i1, wA.z, h1[2]);
                h0[3] = fmaf(i0, wA.w, h0[3]);  h1[3] = fmaf(i1, wA.w, h1[3]);
                h0[4] = fmaf(i0, wB.x, h0[4]);  h1[4] = fmaf(i1, wB.x, h1[4]);
                h0[5] = fmaf(i0, wB.y, h0[5]);  h1[5] = fmaf(i1, wB.y, h1[5]);
                h0[6] = fmaf(i0, wB.z, h0[6]);  h1[6] = fmaf(i1, wB.z, h1[6]);
                h0[7] = fmaf(i0, wB.w, h0[7]);  h1[7] = fmaf(i1, wB.w, h1[7]);
            }

            float4 pA = ((const float4*)s_projw)[ch*2+0];
            float4 pB = ((const float4*)s_projw)[ch*2+1];
            s0 = fmaf(fmaxf(h0[0],0.f), pA.x, s0);  s1 = fmaf(fmaxf(h1[0],0.f), pA.x, s1);
            s0 = fmaf(fmaxf(h0[1],0.f), pA.y, s0);  s1 = fmaf(fmaxf(h1[1],0.f), pA.y, s1);
            s0 = fmaf(fmaxf(h0[2],0.f), pA.z, s0);  s1 = fmaf(fmaxf(h1[2],0.f), pA.z, s1);
            s0 = fmaf(fmaxf(h0[3],0.f), pA.w, s0);  s1 = fmaf(fmaxf(h1[3],0.f), pA.w, s1);
            s0 = fmaf(fmaxf(h0[4],0.f), pB.x, s0);  s1 = fmaf(fmaxf(h1[4],0.f), pB.x, s1);
            s0 = fmaf(fmaxf(h0[5],0.f), pB.y, s0);  s1 = fmaf(fmaxf(h1[5],0.f), pB.y, s1);
            s0 = fmaf(fmaxf(h0[6],0.f), pB.z, s0);  s1 = fmaf(fmaxf(h1[6],0.f), pB.z, s1);
            s0 = fmaf(fmaxf(h0[7],0.f), pB.w, s0);  s1 = fmaf(fmaxf(h1[7],0.f), pB.w, s1);
        }
        sc0 = s0; sc1 = s1;
    }

    // ---- block softmax-max reduction (both samples) ----
    float m0 = sc0, m1 = sc1;
    #pragma unroll
    for (int o = 16; o > 0; o >>= 1) {
        m0 = fmaxf(m0, __shfl_xor_sync(0xffffffffu, m0, o));
        m1 = fmaxf(m1, __shfl_xor_sync(0xffffffffu, m1, o));
    }
    if (lane == 0) { red_max[0][wid] = m0; red_max[1][wid] = m1; }
    __syncthreads();
    if (tid == 0) {
        float a = red_max[0][0], b = red_max[1][0];
        #pragma unroll
        for (int w = 1; w < NWARP; w++) {
            a = fmaxf(a, red_max[0][w]);
            b = fmaxf(b, red_max[1][w]);
        }
        s_smax[0] = a; s_smax[1] = b;
    }
    __syncthreads();

    // ---- exp + weighted sums ----
    float ex0 = active ? __expf(sc0 - s_smax[0]) : 0.f;
    float ex1 = active ? __expf(sc1 - s_smax[1]) : 0.f;
    float se0 = ex0, sg0 = ex0 * g0;
    float se1 = ex1, sg1 = ex1 * g1;
    #pragma unroll
    for (int o = 16; o > 0; o >>= 1) {
        se0 += __shfl_xor_sync(0xffffffffu, se0, o);
        sg0 += __shfl_xor_sync(0xffffffffu, sg0, o);
        se1 += __shfl_xor_sync(0xffffffffu, se1, o);
        sg1 += __shfl_xor_sync(0xffffffffu, sg1, o);
    }
    if (lane == 0) {
        red_se[0][wid] = se0; red_sg[0][wid] = sg0;
        red_se[1][wid] = se1; red_sg[1][wid] = sg1;
    }
    __syncthreads();

    if (tid < NS) {
        int s = tid;
        float tse = 0.f, tsg = 0.f;
        #pragma unroll
        for (int w = 0; w < NWARP; w++) { tse += red_se[s][w]; tsg += red_sg[s][w]; }
        float lin = 0.f;
        #pragma unroll
        for (int f = 0; f < NF; f++) lin += s_lin[s][f];
        out[b0 + s] = lin + s_scal[1] + tsg / tse;
    }
}

extern "C" void kernel_launch(void* const* d_in, const int* in_sizes, int n_in,
                              void* d_out, int out_size) {
    const int* x              = (const int*)d_in[0];
    const float* embed_table  = (const float*)d_in[1];
    const float* linear_table = (const float*)d_in[2];
    const float* linear_bias  = (const float*)d_in[3];
    const float* attn_W       = (const float*)d_in[4];
    const float* attn_b       = (const float*)d_in[5];
    const float* proj_w       = (const float*)d_in[6];
    const float* proj_b       = (const float*)d_in[7];
    const float* fc_w         = (const float*)d_in[8];
    const float* fc_b         = (const float*)d_in[9];
    float* out = (float*)d_out;

    int B = out_size;                 // one output per sample
    int nblocks = (B + NS - 1) / NS;  // B=16384 -> 8192
    afm_kernel<<<nblocks, NTHREADS>>>(x, embed_table, linear_table, linear_bias,
                                      attn_W, attn_b, proj_w, proj_b, fc_w, fc_b, out);
}

// round 6
// speedup vs baseline: 2.2359x; 1.6920x over previous
#include <cuda_runtime.h>
#include <cstdint>

// AFM forward: 2 samples per CTA, 2 pairs x 2 samples per thread.
// cross term = (sum_p e^{s_p} g_p) / (sum_p e^{s_p}),  g_p = inner_p . fc_w

#define NF 24
#define NE 16
#define NA 32
#define NP 276            // 24*23/2
#define NS 2              // samples per block
#define HPT 138           // half the pairs: thread t handles pairs t and t+HPT
#define NTHREADS 160      // 5 warps
#define NWARP 5
#define EPAD 20           // padded row length for s_emb (80B, 16B aligned, bank stride 20)

__global__ __launch_bounds__(NTHREADS) void afm_kernel(
    const int* __restrict__ x_raw,            // [B,24] int32 OR int64 (auto-detect)
    const float* __restrict__ embed_table,    // [V,16]
    const float* __restrict__ linear_table,   // [V,1]
    const float* __restrict__ linear_bias,    // [1]
    const float* __restrict__ attn_W,         // [16,32]
    const float* __restrict__ attn_b,         // [32]
    const float* __restrict__ proj_w,         // [32,1]
    const float* __restrict__ proj_b,         // [1]
    const float* __restrict__ fc_w,           // [16,1]
    const float* __restrict__ fc_b,           // [1]
    float* __restrict__ out)                  // [B,1]
{
    __shared__ float s_emb[NS][NF][EPAD];
    __shared__ float s_W[NE][NA];
    __shared__ int   s_gid[NS][NF];
    __shared__ float s_lin[NS][NF];
    __shared__ float s_attnb[NA];
    __shared__ float s_projw[NA];
    __shared__ float s_fcw[NE];
    __shared__ float s_scal[2];
    __shared__ float red_max[NS][NWARP];
    __shared__ float red_se[NS][NWARP];
    __shared__ float red_sg[NS][NWARP];
    __shared__ float s_smax[NS];

    const int tid  = threadIdx.x;
    const int wid  = tid >> 5;
    const int lane = tid & 31;
    const long long b0 = (long long)blockIdx.x * NS;

    // dtype probe: int64 values < 50000 have zero high words at odd positions.
    const bool is64 = (x_raw[1] == 0) & (x_raw[3] == 0) & (x_raw[5] == 0) & (x_raw[7] == 0);

    // ---- stage indices + linear terms (48 threads) ----
    if (tid < NS * NF) {
        int s = tid / NF;
        int f = tid - s * NF;
        long long flat = (b0 + s) * NF + f;
        int xv = is64 ? x_raw[flat * 2] : x_raw[flat];
        int gid = xv + f * 50000;
        s_gid[s][f] = gid;
        s_lin[s][f] = linear_table[gid];
    }
    for (int t = tid; t < NE * NA; t += NTHREADS)
        ((float*)s_W)[t] = attn_W[t];
    if (tid < NA) {
        s_attnb[tid] = attn_b[tid];
        s_projw[tid] = proj_w[tid];
    }
    if (tid < NE) s_fcw[tid] = fc_w[tid];
    if (tid == 0) {
        s_scal[0] = proj_b[0];
        s_scal[1] = fc_b[0] + linear_bias[0];
    }
    __syncthreads();

    // ---- gather embeddings as float4: NS*24 rows x 4 float4 = 192 loads ----
    for (int t = tid; t < NS * NF * 4; t += NTHREADS) {
        int s = t / (NF * 4);
        int rem = t - s * (NF * 4);
        int f = rem >> 2, q = rem & 3;
        const float4* src = (const float4*)embed_table;
        ((float4*)&s_emb[s][f][0])[q] = src[(long long)s_gid[s][f] * 4 + q];
    }
    __syncthreads();

    // ---- per-thread: pairs A=tid, B=tid+HPT, both samples ----
    const bool active = (tid < HPT);
    float scA0 = -1e30f, scA1 = -1e30f, scB0 = -1e30f, scB1 = -1e30f;
    float gA0 = 0.f, gA1 = 0.f, gB0 = 0.f, gB1 = 0.f;

    if (active) {
        // decode both pairs
        int pA = tid, rA = 0, baseA = 0;
        while (pA >= baseA + (NF - 1 - rA)) { baseA += NF - 1 - rA; rA++; }
        int cA = rA + 1 + (pA - baseA);
        int pB = tid + HPT, rB = 0, baseB = 0;
        while (pB >= baseB + (NF - 1 - rB)) { baseB += NF - 1 - rB; rB++; }
        int cB = rB + 1 + (pB - baseB);

        float inA0[NE], inA1[NE], inB0[NE], inB1[NE];
        #pragma unroll
        for (int q = 0; q < 4; q++) {
            float4 a0 = ((const float4*)&s_emb[0][rA][0])[q];
            float4 c0 = ((const float4*)&s_emb[0][cA][0])[q];
            float4 a1 = ((const float4*)&s_emb[1][rA][0])[q];
            float4 c1 = ((const float4*)&s_emb[1][cA][0])[q];
            inA0[q*4+0]=a0.x*c0.x; inA0[q*4+1]=a0.y*c0.y; inA0[q*4+2]=a0.z*c0.z; inA0[q*4+3]=a0.w*c0.w;
            inA1[q*4+0]=a1.x*c1.x; inA1[q*4+1]=a1.y*c1.y; inA1[q*4+2]=a1.z*c1.z; inA1[q*4+3]=a1.w*c1.w;
            float4 b0v = ((const float4*)&s_emb[0][rB][0])[q];
            float4 d0 = ((const float4*)&s_emb[0][cB][0])[q];
            float4 b1v = ((const float4*)&s_emb[1][rB][0])[q];
            float4 d1 = ((const float4*)&s_emb[1][cB][0])[q];
            inB0[q*4+0]=b0v.x*d0.x; inB0[q*4+1]=b0v.y*d0.y; inB0[q*4+2]=b0v.z*d0.z; inB0[q*4+3]=b0v.w*d0.w;
            inB1[q*4+0]=b1v.x*d1.x; inB1[q*4+1]=b1v.y*d1.y; inB1[q*4+2]=b1v.z*d1.z; inB1[q*4+3]=b1v.w*d1.w;
        }

        // g = inner . fc_w  (4 streams)
        #pragma unroll
        for (int e = 0; e < NE; e++) {
            float fw = s_fcw[e];
            gA0 = fmaf(inA0[e], fw, gA0);
            gA1 = fmaf(inA1[e], fw, gA1);
            gB0 = fmaf(inB0[e], fw, gB0);
            gB1 = fmaf(inB1[e], fw, gB1);
        }

        // h = relu(inner @ W + b); s = h . proj_w + proj_b
        // 4 chunks of 8 attn columns; W/bias/proj loads shared by all 4 streams
        float sA0 = s_scal[0], sA1 = s_scal[0], sB0 = s_scal[0], sB1 = s_scal[0];
        #pragma unroll
        for (int ch = 0; ch < 4; ch++) {
            float4 bA4 = ((const float4*)s_attnb)[ch*2+0];
            float4 bB4 = ((const float4*)s_attnb)[ch*2+1];
            float bias8[8] = {bA4.x,bA4.y,bA4.z,bA4.w,bB4.x,bB4.y,bB4.z,bB4.w};
            float hA0[8], hA1[8], hB0[8], hB1[8];
            #pragma unroll
            for (int j = 0; j < 8; j++) {
                hA0[j] = bias8[j]; hA1[j] = bias8[j];
                hB0[j] = bias8[j]; hB1[j] = bias8[j];
            }

            #pragma unroll
            for (int e = 0; e < NE; e++) {
                const float4* wrow = (const float4*)&s_W[e][0];
                float4 wA4 = wrow[ch*2+0];
                float4 wB4 = wrow[ch*2+1];
                float w8[8] = {wA4.x,wA4.y,wA4.z,wA4.w,wB4.x,wB4.y,wB4.z,wB4.w};
                float a0 = inA0[e], a1 = inA1[e], b0v = inB0[e], b1v = inB1[e];
                #pragma unroll
                for (int j = 0; j < 8; j++) {
                    hA0[j] = fmaf(a0,  w8[j], hA0[j]);
                    hA1[j] = fmaf(a1,  w8[j], hA1[j]);
                    hB0[j] = fmaf(b0v, w8[j], hB0[j]);
                    hB1[j] = fmaf(b1v, w8[j], hB1[j]);
                }
            }

            float4 pA4 = ((const float4*)s_projw)[ch*2+0];
            float4 pB4 = ((const float4*)s_projw)[ch*2+1];
            float p8[8] = {pA4.x,pA4.y,pA4.z,pA4.w,pB4.x,pB4.y,pB4.z,pB4.w};
            #pragma unroll
            for (int j = 0; j < 8; j++) {
                sA0 = fmaf(fmaxf(hA0[j],0.f), p8[j], sA0);
                sA1 = fmaf(fmaxf(hA1[j],0.f), p8[j], sA1);
                sB0 = fmaf(fmaxf(hB0[j],0.f), p8[j], sB0);
                sB1 = fmaf(fmaxf(hB1[j],0.f), p8[j], sB1);
            }
        }
        scA0 = sA0; scA1 = sA1; scB0 = sB0; scB1 = sB1;
    }

    // ---- block softmax-max reduction (both samples) ----
    float m0 = fmaxf(scA0, scB0);
    float m1 = fmaxf(scA1, scB1);
    #pragma unroll
    for (int o = 16; o > 0; o >>= 1) {
        m0 = fmaxf(m0, __shfl_xor_sync(0xffffffffu, m0, o));
        m1 = fmaxf(m1, __shfl_xor_sync(0xffffffffu, m1, o));
    }
    if (lane == 0) { red_max[0][wid] = m0; red_max[1][wid] = m1; }
    __syncthreads();
    if (tid == 0) {
        float a = red_max[0][0], b = red_max[1][0];
        #pragma unroll
        for (int w = 1; w < NWARP; w++) {
            a = fmaxf(a, red_max[0][w]);
            b = fmaxf(b, red_max[1][w]);
        }
        s_smax[0] = a; s_smax[1] = b;
    }
    __syncthreads();

    // ---- exp + weighted sums ----
    const float smax0 = s_smax[0], smax1 = s_smax[1];
    float exA0 = active ? __expf(scA0 - smax0) : 0.f;
    float exA1 = active ? __expf(scA1 - smax1) : 0.f;
    float exB0 = active ? __expf(scB0 - smax0) : 0.f;
    float exB1 = active ? __expf(scB1 - smax1) : 0.f;
    float se0 = exA0 + exB0;
    float se1 = exA1 + exB1;
    float sg0 = exA0 * gA0 + exB0 * gB0;
    float sg1 = exA1 * gA1 + exB1 * gB1;
    #pragma unroll
    for (int o = 16; o > 0; o >>= 1) {
        se0 += __shfl_xor_sync(0xffffffffu, se0, o);
        sg0 += __shfl_xor_sync(0xffffffffu, sg0, o);
        se1 += __shfl_xor_sync(0xffffffffu, se1, o);
        sg1 += __shfl_xor_sync(0xffffffffu, sg1, o);
    }
    if (lane == 0) {
        red_se[0][wid] = se0; red_sg[0][wid] = sg0;
        red_se[1][wid] = se1; red_sg[1][wid] = sg1;
    }
    __syncthreads();

    if (tid < NS) {
        int s = tid;
        float tse = 0.f, tsg = 0.f;
        #pragma unroll
        for (int w = 0; w < NWARP; w++) { tse += red_se[s][w]; tsg += red_sg[s][w]; }
        float lin = 0.f;
        #pragma unroll
        for (int f = 0; f < NF; f++) lin += s_lin[s][f];
        out[b0 + s] = lin + s_scal[1] + tsg / tse;
    }
}

extern "C" void kernel_launch(void* const* d_in, const int* in_sizes, int n_in,
                              void* d_out, int out_size) {
    const int* x              = (const int*)d_in[0];
    const float* embed_table  = (const float*)d_in[1];
    const float* linear_table = (const float*)d_in[2];
    const float* linear_bias  = (const float*)d_in[3];
    const float* attn_W       = (const float*)d_in[4];
    const float* attn_b       = (const float*)d_in[5];
    const float* proj_w       = (const float*)d_in[6];
    const float* proj_b       = (const float*)d_in[7];
    const float* fc_w         = (const float*)d_in[8];
    const float* fc_b         = (const float*)d_in[9];
    float* out = (float*)d_out;

    int B = out_size;                 // one output per sample
    int nblocks = (B + NS - 1) / NS;  // 16384 -> 8192
    afm_kernel<<<nblocks, NTHREADS>>>(x, embed_table, linear_table, linear_bias,
                                      attn_W, attn_b, proj_w, proj_b, fc_w, fc_b, out);
}

// round 9
// speedup vs baseline: 3.2695x; 1.4623x over previous
#include <cuda_runtime.h>
#include <cstdint>

// AFM forward: 2 samples per CTA, 2 pairs x 2 samples per thread,
// hidden-layer GEMV done with packed fma.rn.f32x2 (FFMA2).
// cross term = (sum_p e^{s_p} g_p) / (sum_p e^{s_p}),  g_p = inner_p . fc_w

#define NF 24
#define NE 16
#define NA 32
#define NP 276            // 24*23/2
#define NS 2              // samples per block
#define HPT 138           // thread t handles pairs t and t+HPT
#define NTHREADS 160      // 5 warps
#define NWARP 5
#define EPAD 20           // padded row length for s_emb (80B)

typedef unsigned long long u64;

__device__ __forceinline__ u64 pack2(float lo, float hi) {
    u64 r;
    asm("mov.b64 %0, {%1, %2};" : "=l"(r) : "f"(lo), "f"(hi));
    return r;
}
__device__ __forceinline__ void unpack2(u64 v, float& lo, float& hi) {
    asm("mov.b64 {%0, %1}, %2;" : "=f"(lo), "=f"(hi) : "l"(v));
}
__device__ __forceinline__ u64 fma2(u64 a, u64 b, u64 c) {
    u64 d;
    asm("fma.rn.f32x2 %0, %1, %2, %3;" : "=l"(d) : "l"(a), "l"(b), "l"(c));
    return d;
}

__global__ __launch_bounds__(NTHREADS, 3) void afm_kernel(
    const int* __restrict__ x_raw,            // [B,24] int32 OR int64 (auto-detect)
    const float* __restrict__ embed_table,    // [V,16]
    const float* __restrict__ linear_table,   // [V,1]
    const float* __restrict__ linear_bias,    // [1]
    const float* __restrict__ attn_W,         // [16,32]
    const float* __restrict__ attn_b,         // [32]
    const float* __restrict__ proj_w,         // [32,1]
    const float* __restrict__ proj_b,         // [1]
    const float* __restrict__ fc_w,           // [16,1]
    const float* __restrict__ fc_b,           // [1]
    float* __restrict__ out)                  // [B,1]
{
    __shared__ __align__(16) float s_emb[NS][NF][EPAD];
    __shared__ __align__(16) float s_W[NE][NA];
    __shared__ __align__(16) float s_attnb[NA];
    __shared__ __align__(16) float s_projw[NA];
    __shared__ __align__(16) float s_fcw[NE];
    __shared__ int   s_gid[NS][NF];
    __shared__ float s_lin[NS][NF];
    __shared__ float s_scal[2];
    __shared__ float red_max[NS][NWARP];
    __shared__ float red_se[NS][NWARP];
    __shared__ float red_sg[NS][NWARP];
    __shared__ float s_smax[NS];

    const int tid  = threadIdx.x;
    const int wid  = tid >> 5;
    const int lane = tid & 31;
    const long long b0 = (long long)blockIdx.x * NS;

    // dtype probe: int64 values < 50000 have zero high words at odd positions.
    const bool is64 = (x_raw[1] == 0) & (x_raw[3] == 0) & (x_raw[5] == 0) & (x_raw[7] == 0);

    // ---- stage indices + linear terms ----
    if (tid < NS * NF) {
        int s = tid / NF;
        int f = tid - s * NF;
        long long flat = (b0 + s) * NF + f;
        int xv = is64 ? x_raw[flat * 2] : x_raw[flat];
        int gid = xv + f * 50000;
        s_gid[s][f] = gid;
        s_lin[s][f] = linear_table[gid];
    }
    for (int t = tid; t < NE * NA; t += NTHREADS)
        ((float*)s_W)[t] = attn_W[t];
    if (tid < NA) {
        s_attnb[tid] = attn_b[tid];
        s_projw[tid] = proj_w[tid];
    }
    if (tid < NE) s_fcw[tid] = fc_w[tid];
    if (tid == 0) {
        s_scal[0] = proj_b[0];
        s_scal[1] = fc_b[0] + linear_bias[0];
    }
    __syncthreads();

    // ---- gather embeddings as float4 ----
    for (int t = tid; t < NS * NF * 4; t += NTHREADS) {
        int s = t / (NF * 4);
        int rem = t - s * (NF * 4);
        int f = rem >> 2, q = rem & 3;
        const float4* src = (const float4*)embed_table;
        ((float4*)&s_emb[s][f][0])[q] = src[(long long)s_gid[s][f] * 4 + q];
    }
    __syncthreads();

    // ---- per-thread: pairs A=tid, B=tid+HPT, both samples ----
    const bool active = (tid < HPT);
    float scA0 = -1e30f, scA1 = -1e30f, scB0 = -1e30f, scB1 = -1e30f;
    float gA0 = 0.f, gA1 = 0.f, gB0 = 0.f, gB1 = 0.f;

    if (active) {
        // decode both pairs
        int pA = tid, rA = 0, baseA = 0;
        while (pA >= baseA + (NF - 1 - rA)) { baseA += NF - 1 - rA; rA++; }
        int cA = rA + 1 + (pA - baseA);
        int pB = tid + HPT, rB = 0, baseB = 0;
        while (pB >= baseB + (NF - 1 - rB)) { baseB += NF - 1 - rB; rB++; }
        int cB = rB + 1 + (pB - baseB);

        float inA0[NE], inA1[NE], inB0[NE], inB1[NE];
        #pragma unroll
        for (int q = 0; q < 4; q++) {
            float4 a0 = ((const float4*)&s_emb[0][rA][0])[q];
            float4 c0 = ((const float4*)&s_emb[0][cA][0])[q];
            float4 a1 = ((const float4*)&s_emb[1][rA][0])[q];
            float4 c1 = ((const float4*)&s_emb[1][cA][0])[q];
            inA0[q*4+0]=a0.x*c0.x; inA0[q*4+1]=a0.y*c0.y; inA0[q*4+2]=a0.z*c0.z; inA0[q*4+3]=a0.w*c0.w;
            inA1[q*4+0]=a1.x*c1.x; inA1[q*4+1]=a1.y*c1.y; inA1[q*4+2]=a1.z*c1.z; inA1[q*4+3]=a1.w*c1.w;
            float4 b0v = ((const float4*)&s_emb[0][rB][0])[q];
            float4 d0 = ((const float4*)&s_emb[0][cB][0])[q];
            float4 b1v = ((const float4*)&s_emb[1][rB][0])[q];
            float4 d1 = ((const float4*)&s_emb[1][cB][0])[q];
            inB0[q*4+0]=b0v.x*d0.x; inB0[q*4+1]=b0v.y*d0.y; inB0[q*4+2]=b0v.z*d0.z; inB0[q*4+3]=b0v.w*d0.w;
            inB1[q*4+0]=b1v.x*d1.x; inB1[q*4+1]=b1v.y*d1.y; inB1[q*4+2]=b1v.z*d1.z; inB1[q*4+3]=b1v.w*d1.w;
        }

        // g = inner . fc_w  (4 streams)
        #pragma unroll
        for (int e = 0; e < NE; e++) {
            float fw = s_fcw[e];
            gA0 = fmaf(inA0[e], fw, gA0);
            gA1 = fmaf(inA1[e], fw, gA1);
            gB0 = fmaf(inB0[e], fw, gB0);
            gB1 = fmaf(inB1[e], fw, gB1);
        }

        // h = relu(inner @ W + b); s = h . proj_w + proj_b
        // 4 chunks of 8 attn cols = 4 packed f32x2 accumulators per stream.
        // W pairs load as LDS.64 (no pack); only {i,i} broadcast needs a pack.
        float sA0 = s_scal[0], sA1 = s_scal[0], sB0 = s_scal[0], sB1 = s_scal[0];
        #pragma unroll
        for (int ch = 0; ch < 4; ch++) {
            const u64* bb = (const u64*)&s_attnb[ch*8];
            u64 hA0[4], hA1[4], hB0[4], hB1[4];
            #pragma unroll
            for (int j = 0; j < 4; j++) {
                u64 bj = bb[j];
                hA0[j] = bj; hA1[j] = bj; hB0[j] = bj; hB1[j] = bj;
            }

            #pragma unroll
            for (int e = 0; e < NE; e++) {
                const u64* wr = (const u64*)&s_W[e][ch*8];
                u64 iA0 = pack2(inA0[e], inA0[e]);
                u64 iA1 = pack2(inA1[e], inA1[e]);
                u64 iB0 = pack2(inB0[e], inB0[e]);
                u64 iB1 = pack2(inB1[e], inB1[e]);
                #pragma unroll
                for (int j = 0; j < 4; j++) {
                    u64 w = wr[j];
                    hA0[j] = fma2(iA0, w, hA0[j]);
                    hA1[j] = fma2(iA1, w, hA1[j]);
                    hB0[j] = fma2(iB0, w, hB0[j]);
                    hB1[j] = fma2(iB1, w, hB1[j]);
                }
            }

            #pragma unroll
            for (int j = 0; j < 4; j++) {
                float p0 = s_projw[ch*8 + j*2 + 0];
                float p1 = s_projw[ch*8 + j*2 + 1];
                float lo, hi;
                unpack2(hA0[j], lo, hi);
                sA0 = fmaf(fmaxf(lo,0.f), p0, sA0);
                sA0 = fmaf(fmaxf(hi,0.f), p1, sA0);
                unpack2(hA1[j], lo, hi);
                sA1 = fmaf(fmaxf(lo,0.f), p0, sA1);
                sA1 = fmaf(fmaxf(hi,0.f), p1, sA1);
                unpack2(hB0[j], lo, hi);
                sB0 = fmaf(fmaxf(lo,0.f), p0, sB0);
                sB0 = fmaf(fmaxf(hi,0.f), p1, sB0);
                unpack2(hB1[j], lo, hi);
                sB1 = fmaf(fmaxf(lo,0.f), p0, sB1);
                sB1 = fmaf(fmaxf(hi,0.f), p1, sB1);
            }
        }
        scA0 = sA0; scA1 = sA1; scB0 = sB0; scB1 = sB1;
    }

    // ---- block softmax-max reduction (both samples) ----
    float m0 = fmaxf(scA0, scB0);
    float m1 = fmaxf(scA1, scB1);
    #pragma unroll
    for (int o = 16; o > 0; o >>= 1) {
        m0 = fmaxf(m0, __shfl_xor_sync(0xffffffffu, m0, o));
        m1 = fmaxf(m1, __shfl_xor_sync(0xffffffffu, m1, o));
    }
    if (lane == 0) { red_max[0][wid] = m0; red_max[1][wid] = m1; }
    __syncthreads();
    if (tid == 0) {
        float a = red_max[0][0], b = red_max[1][0];
        #pragma unroll
        for (int w = 1; w < NWARP; w++) {
            a = fmaxf(a, red_max[0][w]);
            b = fmaxf(b, red_max[1][w]);
        }
        s_smax[0] = a; s_smax[1] = b;
    }
    __syncthreads();

    // ---- exp + weighted sums ----
    const float smax0 = s_smax[0], smax1 = s_smax[1];
    float exA0 = active ? __expf(scA0 - smax0) : 0.f;
    float exA1 = active ? __expf(scA1 - smax1) : 0.f;
    float exB0 = active ? __expf(scB0 - smax0) : 0.f;
    float exB1 = active ? __expf(scB1 - smax1) : 0.f;
    float se0 = exA0 + exB0;
    float se1 = exA1 + exB1;
    float sg0 = exA0 * gA0 + exB0 * gB0;
    float sg1 = exA1 * gA1 + exB1 * gB1;
    #pragma unroll
    for (int o = 16; o > 0; o >>= 1) {
        se0 += __shfl_xor_sync(0xffffffffu, se0, o);
        sg0 += __shfl_xor_sync(0xffffffffu, sg0, o);
        se1 += __shfl_xor_sync(0xffffffffu, se1, o);
        sg1 += __shfl_xor_sync(0xffffffffu, sg1, o);
    }
    if (lane == 0) {
        red_se[0][wid] = se0; red_sg[0][wid] = sg0;
        red_se[1][wid] = se1; red_sg[1][wid] = sg1;
    }
    __syncthreads();

    if (tid < NS) {
        int s = tid;
        float tse = 0.f, tsg = 0.f;
        #pragma unroll
        for (int w = 0; w < NWARP; w++) { tse += red_se[s][w]; tsg += red_sg[s][w]; }
        float lin = 0.f;
        #pragma unroll
        for (int f = 0; f < NF; f++) lin += s_lin[s][f];
        out[b0 + s] = lin + s_scal[1] + tsg / tse;
    }
}

extern "C" void kernel_launch(void* const* d_in, const int* in_sizes, int n_in,
                              void* d_out, int out_size) {
    const int* x              = (const int*)d_in[0];
    const float* embed_table  = (const float*)d_in[1];
    const float* linear_table = (const float*)d_in[2];
    const float* linear_bias  = (const float*)d_in[3];
    const float* attn_W       = (const float*)d_in[4];
    const float* attn_b       = (const float*)d_in[5];
    const float* proj_w       = (const float*)d_in[6];
    const float* proj_b       = (const float*)d_in[7];
    const float* fc_w         = (const float*)d_in[8];
    const float* fc_b         = (const float*)d_in[9];
    float* out = (float*)d_out;

    int B = out_size;                 // one output per sample
    int nblocks = (B + NS - 1) / NS;  // 16384 -> 8192
    afm_kernel<<<nblocks, NTHREADS>>>(x, embed_table, linear_table, linear_bias,
                                      attn_W, attn_b, proj_w, proj_b, fc_w, fc_b, out);
}